// round 6
// baseline (speedup 1.0000x reference)
#include <cuda_runtime.h>
#include <cuda_fp16.h>
#include <math.h>
#include <stdint.h>

// Problem dims
#define NB   1024
#define LL   128
#define HH   512
#define OO   32000
#define H2   1024   // 2H
#define H3   1536   // 3H

#define HPAD 40     // smem row stride in halfs -> ldmatrix conflict-free

// ---------------- scratch (device globals; no allocation allowed) -----------
__device__ __align__(16) __half g_cat_h [NB * H2];
__device__ __align__(16) __half g_x_h   [NB * HH];
__device__ __align__(16) __half g_hid_h [NB * HH];
__device__ __align__(16) __half g_hnew_h[NB * HH];
__device__ float g_gx [NB * H3];
__device__ float g_gh [NB * H3];
__device__ __align__(16) float g_rowsum[NB];

// fp16 weight copies
__device__ __align__(16) __half g_attnW_h[LL * H2];
__device__ __align__(16) __half g_combW_h[HH * H2];
__device__ __align__(16) __half g_Wih_h  [H3 * HH];
__device__ __align__(16) __half g_Whh_h  [H3 * HH];
__device__ __align__(16) __half g_outW_h [OO * HH];

// ---------------- PTX helpers ------------------------------------------------
__device__ __forceinline__ uint32_t smem_u32(const void* p)
{
    return (uint32_t)__cvta_generic_to_shared(p);
}
__device__ __forceinline__ void cpasync16(uint32_t s, const void* g)
{
    asm volatile("cp.async.cg.shared.global [%0], [%1], 16;\n" :: "r"(s), "l"(g));
}
__device__ __forceinline__ void cp_commit() { asm volatile("cp.async.commit_group;\n"); }
__device__ __forceinline__ void cp_wait1()  { asm volatile("cp.async.wait_group 1;\n"); }

__device__ __forceinline__ void ldsm_x4(uint32_t* r, uint32_t addr)
{
    asm volatile("ldmatrix.sync.aligned.m8n8.x4.shared.b16 {%0,%1,%2,%3}, [%4];\n"
                 : "=r"(r[0]), "=r"(r[1]), "=r"(r[2]), "=r"(r[3]) : "r"(addr));
}
__device__ __forceinline__ void ldsm_x2(uint32_t* r, uint32_t addr)
{
    asm volatile("ldmatrix.sync.aligned.m8n8.x2.shared.b16 {%0,%1}, [%2];\n"
                 : "=r"(r[0]), "=r"(r[1]) : "r"(addr));
}
__device__ __forceinline__ void mma_f16(float* d, const uint32_t* a, const uint32_t* b)
{
    asm volatile(
        "mma.sync.aligned.m16n8k16.row.col.f32.f16.f16.f32 "
        "{%0,%1,%2,%3}, {%4,%5,%6,%7}, {%8,%9}, {%0,%1,%2,%3};\n"
        : "+f"(d[0]), "+f"(d[1]), "+f"(d[2]), "+f"(d[3])
        : "r"(a[0]), "r"(a[1]), "r"(a[2]), "r"(a[3]), "r"(b[0]), "r"(b[1]));
}

// =============================================================================
// Generic fp16 HMMA GEMM body: BM=BN=128, BK=32, 256 thr, warp tile 64x32.
// mode 0: fp32 C+bias. mode 1: relu -> fp16 Ch. mode 3: atomicAdd into C (no bias).
// =============================================================================
#define HSTAGE (2 * 128 * HPAD)

__device__ __forceinline__ void gemm128_body(
    const __half* __restrict__ A, const __half* __restrict__ W,
    const float* __restrict__ bias,
    float* __restrict__ C, __half* __restrict__ Ch,
    int Nd, int Kstride, int Ksub, int koff, int mode, __half* smh)
{
    const int bm   = blockIdx.y * 128;
    const int bn   = blockIdx.x * 128;
    const int tid  = threadIdx.x;
    const int warp = tid >> 5;
    const int lane = tid & 31;
    const int gid  = lane >> 2;
    const int tig  = lane & 3;
    const int wm   = (warp >> 2) * 64;
    const int wn   = (warp & 3) * 32;

    const int arow = wm + (lane & 15);
    const int acol = (lane >> 4) * 8;
    const int brow = wn + (lane & 7);
    const int bcol = ((lane >> 3) & 1) * 8;

    const uint32_t smem_b = smem_u32(smh);

    float acc[4][4][4];
    #pragma unroll
    for (int i = 0; i < 4; i++)
        #pragma unroll
        for (int j = 0; j < 4; j++)
            #pragma unroll
            for (int r = 0; r < 4; r++) acc[i][j][r] = 0.f;

    const __half* Ag = A + (size_t)bm * Kstride + koff;
    const __half* Wg = W + (size_t)bn * Kstride + koff;
    const int nIter = Ksub >> 5;

    auto load_tiles = [&](int it, int stg) {
        const __half* a_src = Ag + it * 32;
        const __half* w_src = Wg + it * 32;
        uint32_t aBase = smem_b + (stg * HSTAGE) * 2u;
        uint32_t bBase = aBase + 128 * HPAD * 2u;
        #pragma unroll
        for (int j = 0; j < 2; j++) {
            int idx = tid + j * 256;
            int r = idx >> 2;
            int c = (idx & 3) * 8;
            cpasync16(aBase + (r * HPAD + c) * 2u, a_src + (size_t)r * Kstride + c);
        }
        #pragma unroll
        for (int j = 0; j < 2; j++) {
            int idx = tid + j * 256;
            int r = idx >> 2;
            int c = (idx & 3) * 8;
            cpasync16(bBase + (r * HPAD + c) * 2u, w_src + (size_t)r * Kstride + c);
        }
    };

    load_tiles(0, 0); cp_commit();
    load_tiles(1, 1); cp_commit();

    int stg = 0;
    for (int it = 0; it < nIter; ++it) {
        cp_wait1();
        __syncthreads();

        if (it + 2 < nIter) load_tiles(it + 2, (stg + 2) % 3);
        cp_commit();

        const uint32_t aBase = smem_b + (stg * HSTAGE) * 2u;
        const uint32_t bBase = aBase + 128 * HPAD * 2u;

        #pragma unroll
        for (int kk = 0; kk < 2; kk++) {
            uint32_t af[4][4], bf[4][2];
            #pragma unroll
            for (int mt = 0; mt < 4; mt++)
                ldsm_x4(af[mt], aBase + (((arow + mt * 16) * HPAD) + kk * 16 + acol) * 2u);
            #pragma unroll
            for (int nt = 0; nt < 4; nt++)
                ldsm_x2(bf[nt], bBase + (((brow + nt * 8) * HPAD) + kk * 16 + bcol) * 2u);
            #pragma unroll
            for (int mt = 0; mt < 4; mt++)
                #pragma unroll
                for (int nt = 0; nt < 4; nt++)
                    mma_f16(acc[mt][nt], af[mt], bf[nt]);
        }
        stg = (stg + 1) % 3;
    }

    #pragma unroll
    for (int mt = 0; mt < 4; mt++) {
        int r0 = bm + wm + mt * 16 + gid;
        #pragma unroll
        for (int nt = 0; nt < 4; nt++) {
            int c0 = bn + wn + nt * 8 + tig * 2;
            if (mode == 3) {
                atomicAdd(&C[(size_t)(r0    ) * Nd + c0],     acc[mt][nt][0]);
                atomicAdd(&C[(size_t)(r0    ) * Nd + c0 + 1], acc[mt][nt][1]);
                atomicAdd(&C[(size_t)(r0 + 8) * Nd + c0],     acc[mt][nt][2]);
                atomicAdd(&C[(size_t)(r0 + 8) * Nd + c0 + 1], acc[mt][nt][3]);
                continue;
            }
            float b0v = bias[c0], b1v = bias[c0 + 1];
            float v0 = acc[mt][nt][0] + b0v;
            float v1 = acc[mt][nt][1] + b1v;
            float v2 = acc[mt][nt][2] + b0v;
            float v3 = acc[mt][nt][3] + b1v;
            if (mode == 1) {
                v0 = fmaxf(v0, 0.f); v1 = fmaxf(v1, 0.f);
                v2 = fmaxf(v2, 0.f); v3 = fmaxf(v3, 0.f);
                *(__half2*)&Ch[(size_t)(r0    ) * Nd + c0] = __floats2half2_rn(v0, v1);
                *(__half2*)&Ch[(size_t)(r0 + 8) * Nd + c0] = __floats2half2_rn(v2, v3);
            } else {
                *(float2*)&C[(size_t)(r0    ) * Nd + c0] = make_float2(v0, v1);
                *(float2*)&C[(size_t)(r0 + 8) * Nd + c0] = make_float2(v2, v3);
            }
        }
    }
}

__global__ __launch_bounds__(256, 2)
void k_gemm_f16(const __half* __restrict__ A, const __half* __restrict__ W,
                const float* __restrict__ bias,
                float* __restrict__ C, __half* __restrict__ Ch,
                int Nd, int Kstride, int Ksub, int mode)
{
    extern __shared__ __half smh[];
    gemm128_body(A, W, bias, C, Ch, Nd, Kstride, Ksub,
                 blockIdx.z * Ksub, mode, smh);
}

// fused GRU pair: z=0 -> gx = x@W_ih^T+b_ih ; z=1 -> gh = hid@W_hh^T+b_hh
__global__ __launch_bounds__(256, 2)
void k_gemm_gru(const __half* __restrict__ A0, const __half* __restrict__ A1,
                const __half* __restrict__ W0, const __half* __restrict__ W1,
                const float* __restrict__ b0, const float* __restrict__ b1,
                float* __restrict__ C0, float* __restrict__ C1)
{
    extern __shared__ __half smh[];
    const int z = blockIdx.z;
    gemm128_body(z ? A1 : A0, z ? W1 : W0, z ? b1 : b0,
                 z ? C1 : C0, nullptr, H3, HH, HH, 0, 0, smh);
}

// =============================================================================
// Big output GEMM: CTA 128x256, warp tile 64x64, BK=32, 3-stage.
// Fused bias + exp-sum into g_rowsum.
// =============================================================================
#define HSTAGE2 (384 * HPAD)     // halfs per stage (A 128 rows + B 256 rows)
#define OSMEM (3 * HSTAGE2 * 2 + 1024)

__global__ __launch_bounds__(256, 1)
void k_out_f16(const __half* __restrict__ A, const __half* __restrict__ W,
               const float* __restrict__ bias, float* __restrict__ C,
               float* __restrict__ rowsum)
{
    extern __shared__ __half smh[];
    float* sbias = (float*)(smh + 3 * HSTAGE2);

    const int bm   = blockIdx.x * 128;   // M fastest -> B strip L2 reuse
    const int bn   = blockIdx.y * 256;
    const int tid  = threadIdx.x;
    const int warp = tid >> 5;
    const int lane = tid & 31;
    const int gid  = lane >> 2;
    const int tig  = lane & 3;
    const int wm   = (warp >> 2) * 64;
    const int wn   = (warp & 3) * 64;

    const int arow = wm + (lane & 15);
    const int acol = (lane >> 4) * 8;
    // B ldsm_x4 covers an nt-pair (16 n-rows)
    const int brow = wn + ((lane >> 4) * 8) + (lane & 7);   // + pair*16
    const int bcol = ((lane >> 3) & 1) * 8;                 // + kk*16

    const uint32_t smem_b = smem_u32(smh);

    sbias[tid] = bias[bn + tid];

    float acc[4][8][4];
    #pragma unroll
    for (int i = 0; i < 4; i++)
        #pragma unroll
        for (int j = 0; j < 8; j++)
            #pragma unroll
            for (int r = 0; r < 4; r++) acc[i][j][r] = 0.f;

    const __half* Ag = A + (size_t)bm * HH;
    const __half* Wg = W + (size_t)bn * HH;
    const int nIter = HH >> 5;   // 16

    auto load_tiles = [&](int it, int stg) {
        const __half* a_src = Ag + it * 32;
        const __half* w_src = Wg + it * 32;
        uint32_t aBase = smem_b + (stg * HSTAGE2) * 2u;
        uint32_t bBase = aBase + 128 * HPAD * 2u;
        #pragma unroll
        for (int j = 0; j < 2; j++) {            // A: 512 chunks
            int idx = tid + j * 256;
            int r = idx >> 2;
            int c = (idx & 3) * 8;
            cpasync16(aBase + (r * HPAD + c) * 2u, a_src + (size_t)r * HH + c);
        }
        #pragma unroll
        for (int j = 0; j < 4; j++) {            // B: 1024 chunks
            int idx = tid + j * 256;
            int r = idx >> 2;
            int c = (idx & 3) * 8;
            cpasync16(bBase + (r * HPAD + c) * 2u, w_src + (size_t)r * HH + c);
        }
    };

    load_tiles(0, 0); cp_commit();
    load_tiles(1, 1); cp_commit();

    int stg = 0;
    for (int it = 0; it < nIter; ++it) {
        cp_wait1();
        __syncthreads();

        if (it + 2 < nIter) load_tiles(it + 2, (stg + 2) % 3);
        cp_commit();

        const uint32_t aBase = smem_b + (stg * HSTAGE2) * 2u;
        const uint32_t bBase = aBase + 128 * HPAD * 2u;

        #pragma unroll
        for (int kk = 0; kk < 2; kk++) {
            uint32_t af[4][4], bf[4][4];
            #pragma unroll
            for (int mt = 0; mt < 4; mt++)
                ldsm_x4(af[mt], aBase + (((arow + mt * 16) * HPAD) + kk * 16 + acol) * 2u);
            #pragma unroll
            for (int np = 0; np < 4; np++)
                ldsm_x4(bf[np], bBase + (((brow + np * 16) * HPAD) + kk * 16 + bcol) * 2u);
            #pragma unroll
            for (int mt = 0; mt < 4; mt++)
                #pragma unroll
                for (int np = 0; np < 4; np++) {
                    mma_f16(acc[mt][2 * np],     af[mt], &bf[np][0]);
                    mma_f16(acc[mt][2 * np + 1], af[mt], &bf[np][2]);
                }
        }
        stg = (stg + 1) % 3;
    }

    // epilogue: bias + exp-sum + stores
    #pragma unroll
    for (int mt = 0; mt < 4; mt++) {
        int r0 = bm + wm + mt * 16 + gid;
        float sum_lo = 0.f, sum_hi = 0.f;
        #pragma unroll
        for (int nt = 0; nt < 8; nt++) {
            int cl = wn + nt * 8 + tig * 2;      // local col in [0,256)
            int c0 = bn + cl;
            float b0v = sbias[cl], b1v = sbias[cl + 1];
            float v0 = acc[mt][nt][0] + b0v;
            float v1 = acc[mt][nt][1] + b1v;
            float v2 = acc[mt][nt][2] + b0v;
            float v3 = acc[mt][nt][3] + b1v;
            sum_lo += __expf(v0) + __expf(v1);
            sum_hi += __expf(v2) + __expf(v3);
            *(float2*)&C[(size_t)(r0    ) * OO + c0] = make_float2(v0, v1);
            *(float2*)&C[(size_t)(r0 + 8) * OO + c0] = make_float2(v2, v3);
        }
        sum_lo += __shfl_xor_sync(0xffffffff, sum_lo, 1);
        sum_lo += __shfl_xor_sync(0xffffffff, sum_lo, 2);
        sum_hi += __shfl_xor_sync(0xffffffff, sum_hi, 1);
        sum_hi += __shfl_xor_sync(0xffffffff, sum_hi, 2);
        if (tig == 0) {
            atomicAdd(&rowsum[r0],     sum_lo);
            atomicAdd(&rowsum[r0 + 8], sum_hi);
        }
    }
}

// ---------------- small kernels ----------------------------------------------
__global__ void k_f2h(const float4* __restrict__ src, __half2* __restrict__ dst, int n4)
{
    int i = blockIdx.x * blockDim.x + threadIdx.x;
    if (i < n4) {
        float4 v = src[i];
        dst[2 * i]     = __floats2half2_rn(v.x, v.y);
        dst[2 * i + 1] = __floats2half2_rn(v.z, v.w);
    }
}

__global__ void k_build_cat(const int* __restrict__ ids,
                            const float* __restrict__ hidden,
                            const float* __restrict__ emb)
{
    int n = blockIdx.x;
    int id = ids[n];
    int i = threadIdx.x;
    float4 e = ((const float4*)(emb    + (size_t)id * HH))[i];
    float4 h = ((const float4*)(hidden + (size_t)n  * HH))[i];

    __half2* c = (__half2*)(g_cat_h + (size_t)n * H2);
    c[2 * i]           = __floats2half2_rn(e.x, e.y);
    c[2 * i + 1]       = __floats2half2_rn(e.z, e.w);
    c[256 + 2 * i]     = __floats2half2_rn(h.x, h.y);
    c[256 + 2 * i + 1] = __floats2half2_rn(h.z, h.w);

    __half2* hh = (__half2*)(g_hid_h + (size_t)n * HH);
    hh[2 * i]     = __floats2half2_rn(h.x, h.y);
    hh[2 * i + 1] = __floats2half2_rn(h.z, h.w);
}

// zero attn_w (1024x128 fp32) + rowsum
__global__ void k_zero(float* __restrict__ attn_w)
{
    int i = blockIdx.x * 256 + threadIdx.x;
    ((float4*)attn_w)[i] = make_float4(0.f, 0.f, 0.f, 0.f);
    if (blockIdx.x == 0)
        ((float4*)g_rowsum)[threadIdx.x] = make_float4(0.f, 0.f, 0.f, 0.f);
}

__global__ void k_softmax128(float* __restrict__ x, const float* __restrict__ b)
{
    __shared__ float red[128];
    int n = blockIdx.x;
    int t = threadIdx.x;
    float* row = x + (size_t)n * LL;
    float v = row[t] + b[t];

    red[t] = v; __syncthreads();
    for (int s = 64; s > 0; s >>= 1) {
        if (t < s) red[t] = fmaxf(red[t], red[t + s]);
        __syncthreads();
    }
    float m = red[0]; __syncthreads();

    float e = expf(v - m);
    red[t] = e; __syncthreads();
    for (int s = 64; s > 0; s >>= 1) {
        if (t < s) red[t] += red[t + s];
        __syncthreads();
    }
    row[t] = e / red[0];
}

__global__ void k_attn_apply(const float* __restrict__ eo,
                             const float* __restrict__ mask,
                             const float* __restrict__ w)
{
    __shared__ float ws[LL];
    int n = blockIdx.x;
    int t = threadIdx.x;
    ws[t] = w[(size_t)n * LL + t];
    __syncthreads();

    const float4* e4 = (const float4*)(eo   + (size_t)n * LL * HH) + t;
    const float4* m4 = (const float4*)(mask + (size_t)n * LL * HH) + t;

    float4 acc = make_float4(0.f, 0.f, 0.f, 0.f);
    #pragma unroll 4
    for (int l = 0; l < LL; l++) {
        float4 e = e4[(size_t)l * 128];
        float4 m = m4[(size_t)l * 128];
        float  wv = ws[l];
        acc.x = fmaf(wv, e.x * m.x, acc.x);
        acc.y = fmaf(wv, e.y * m.y, acc.y);
        acc.z = fmaf(wv, e.z * m.z, acc.z);
        acc.w = fmaf(wv, e.w * m.w, acc.w);
    }
    __half2* dst = (__half2*)(g_cat_h + (size_t)n * H2 + HH);
    dst[2 * t]     = __floats2half2_rn(acc.x, acc.y);
    dst[2 * t + 1] = __floats2half2_rn(acc.z, acc.w);
}

__global__ void k_gru(const float* __restrict__ hidden,
                      float* __restrict__ h_new)
{
    int idx = blockIdx.x * blockDim.x + threadIdx.x;
    if (idx >= NB * HH) return;
    int n = idx >> 9;
    int h = idx & (HH - 1);
    size_t base = (size_t)n * H3 + h;

    float xr = g_gx[base], xz = g_gx[base + HH], xn = g_gx[base + 2 * HH];
    float hr = g_gh[base], hz = g_gh[base + HH], hn = g_gh[base + 2 * HH];

    float r = 1.f / (1.f + expf(-(xr + hr)));
    float z = 1.f / (1.f + expf(-(xz + hz)));
    float nn = tanhf(xn + r * hn);
    float hv = (1.f - z) * nn + z * hidden[idx];
    h_new[idx] = hv;
    g_hnew_h[idx] = __float2half_rn(hv);
}

__global__ void k_sub_lse(float* __restrict__ x)
{
    int n = blockIdx.x;
    float lse = __logf(g_rowsum[n]);
    float4* row = (float4*)(x + (size_t)n * OO);
    for (int i = threadIdx.x; i < OO / 4; i += blockDim.x) {
        float4 v = row[i];
        v.x -= lse; v.y -= lse; v.z -= lse; v.w -= lse;
        row[i] = v;
    }
}

// ---------------- launch ------------------------------------------------------
extern "C" void kernel_launch(void* const* d_in, const int* in_sizes, int n_in,
                              void* d_out, int out_size)
{
    const int*   ids     = (const int*)  d_in[0];
    const float* hidden  = (const float*)d_in[1];
    const float* eo      = (const float*)d_in[2];
    const float* mask    = (const float*)d_in[3];
    const float* emb     = (const float*)d_in[4];
    const float* attn_W  = (const float*)d_in[5];
    const float* attn_b  = (const float*)d_in[6];
    const float* comb_W  = (const float*)d_in[7];
    const float* comb_b  = (const float*)d_in[8];
    const float* W_ih    = (const float*)d_in[9];
    const float* W_hh    = (const float*)d_in[10];
    const float* b_ih    = (const float*)d_in[11];
    const float* b_hh    = (const float*)d_in[12];
    const float* out_W   = (const float*)d_in[13];
    const float* out_b   = (const float*)d_in[14];

    float* out    = (float*)d_out;                       // [N, O]
    float* h_new  = out + (size_t)NB * OO;               // [N, H]
    float* attn_w = h_new + (size_t)NB * HH;             // [N, L]

    float* gxp;   cudaGetSymbolAddress((void**)&gxp,  g_gx);
    float* ghp;   cudaGetSymbolAddress((void**)&ghp,  g_gh);
    float* rsp;   cudaGetSymbolAddress((void**)&rsp,  g_rowsum);
    __half *catp, *xp, *hidp, *hnp, *aWp, *cWp, *ihp, *hhp, *oWp;
    cudaGetSymbolAddress((void**)&catp, g_cat_h);
    cudaGetSymbolAddress((void**)&xp,   g_x_h);
    cudaGetSymbolAddress((void**)&hidp, g_hid_h);
    cudaGetSymbolAddress((void**)&hnp,  g_hnew_h);
    cudaGetSymbolAddress((void**)&aWp,  g_attnW_h);
    cudaGetSymbolAddress((void**)&cWp,  g_combW_h);
    cudaGetSymbolAddress((void**)&ihp,  g_Wih_h);
    cudaGetSymbolAddress((void**)&hhp,  g_Whh_h);
    cudaGetSymbolAddress((void**)&oWp,  g_outW_h);

    const int SMEM = 3 * HSTAGE * sizeof(__half);
    cudaFuncSetAttribute(k_gemm_f16, cudaFuncAttributeMaxDynamicSharedMemorySize, SMEM);
    cudaFuncSetAttribute(k_gemm_gru, cudaFuncAttributeMaxDynamicSharedMemorySize, SMEM);
    cudaFuncSetAttribute(k_out_f16, cudaFuncAttributeMaxDynamicSharedMemorySize, OSMEM);

    // 0. weight conversions
    k_f2h<<<(LL * H2 / 4 + 255) / 256, 256>>>((const float4*)attn_W, (__half2*)aWp, LL * H2 / 4);
    k_f2h<<<(HH * H2 / 4 + 255) / 256, 256>>>((const float4*)comb_W, (__half2*)cWp, HH * H2 / 4);
    k_f2h<<<(H3 * HH / 4 + 255) / 256, 256>>>((const float4*)W_ih, (__half2*)ihp, H3 * HH / 4);
    k_f2h<<<(H3 * HH / 4 + 255) / 256, 256>>>((const float4*)W_hh, (__half2*)hhp, H3 * HH / 4);
    k_f2h<<<((size_t)OO * HH / 4 + 255) / 256, 256>>>((const float4*)out_W, (__half2*)oWp, OO * HH / 4);

    // 1. cat = [emb|hidden] fp16 ; zero attn_w + rowsum
    k_build_cat<<<NB, 128>>>(ids, hidden, emb);
    k_zero<<<NB * LL / 1024, 256>>>(attn_w);

    // 2. attn logits, split-K=4, atomic accumulate
    {
        dim3 grid(LL / 128, NB / 128, 4);
        k_gemm_f16<<<grid, 256, SMEM>>>(catp, aWp, nullptr, attn_w, nullptr,
                                        LL, H2, H2 / 4, 3);
    }
    // 3. softmax over L (adds bias)
    k_softmax128<<<NB, 128>>>(attn_w, attn_b);
    // 4. attn_applied (fused mask)
    k_attn_apply<<<NB, 128>>>(eo, mask, attn_w);
    // 5. comb + relu -> fp16 x
    {
        dim3 grid(HH / 128, NB / 128);
        k_gemm_f16<<<grid, 256, SMEM>>>(catp, cWp, comb_b, nullptr, xp,
                                        HH, H2, H2, 1);
    }
    // 6/7. fused GRU GEMM pair
    {
        dim3 grid(H3 / 128, NB / 128, 2);
        k_gemm_gru<<<grid, 256, SMEM>>>(xp, hidp, ihp, hhp, b_ih, b_hh, gxp, ghp);
    }
    // 8. GRU gates
    k_gru<<<(NB * HH + 255) / 256, 256>>>(hidden, h_new);

    // 9. big output GEMM (128x256 CTA, 64x64 warps) + fused exp-sum
    {
        dim3 grid(NB / 128, OO / 256);   // M fastest
        k_out_f16<<<grid, 256, OSMEM>>>(hnp, oWp, out_b, out, rsp);
    }
    // 10. finalize log-softmax
    k_sub_lse<<<NB, 256>>>(out);
}